// round 2
// baseline (speedup 1.0000x reference)
#include <cuda_runtime.h>
#include <cstdint>

#define NUM_USERS 100000
#define NUM_ITEMS 150000
#define N_NODES   250000
#define DIM       64
#define N_EDGES   2000000
#define EPS_F     0.2f

// Scratch (device globals: allocation-free, graph-capturable)
__device__ float g_emb [(size_t)N_NODES * DIM];  // current layer input
__device__ float g_next[(size_t)N_NODES * DIM];  // scatter target (pre-zeroed)
__device__ float g_acc [(size_t)N_NODES * DIM];  // running sum of layers

// ---------------------------------------------------------------------------
// init: emb = acc = concat(user_emb, item_emb); next = 0
// 16 lanes (float4 chunks) per node
// ---------------------------------------------------------------------------
__global__ void init_k(const float* __restrict__ ue, const float* __restrict__ ie) {
    unsigned t = blockIdx.x * blockDim.x + threadIdx.x;
    if (t >= (unsigned)N_NODES * 16u) return;
    unsigned node = t >> 4;
    unsigned c = t & 15u;
    float4 v;
    if (node < NUM_USERS)
        v = reinterpret_cast<const float4*>(ue)[(size_t)node * 16 + c];
    else
        v = reinterpret_cast<const float4*>(ie)[(size_t)(node - NUM_USERS) * 16 + c];
    reinterpret_cast<float4*>(g_emb)[t] = v;
    reinterpret_cast<float4*>(g_acc)[t] = v;
    reinterpret_cast<float4*>(g_next)[t] = make_float4(0.f, 0.f, 0.f, 0.f);
}

// ---------------------------------------------------------------------------
// scatter: next[dst] += vals[e] * emb[src]   (16 lanes per edge, v4 reduction)
// ---------------------------------------------------------------------------
__global__ void scatter_k(const int* __restrict__ src,
                          const int* __restrict__ dst,
                          const float* __restrict__ vals) {
    unsigned t = blockIdx.x * blockDim.x + threadIdx.x;
    unsigned e = t >> 4;
    if (e >= (unsigned)N_EDGES) return;
    unsigned c = t & 15u;
    int s = __ldg(src + e);
    int d = __ldg(dst + e);
    float v = __ldg(vals + e);
    float4 x = reinterpret_cast<const float4*>(g_emb)[(size_t)s * 16 + c];
    x.x *= v; x.y *= v; x.z *= v; x.w *= v;
    float4* p = reinterpret_cast<float4*>(g_next) + (size_t)d * 16 + c;
    asm volatile("red.global.add.v4.f32 [%0], {%1, %2, %3, %4};"
                 :: "l"(p), "f"(x.x), "f"(x.y), "f"(x.z), "f"(x.w)
                 : "memory");
}

// ---------------------------------------------------------------------------
// node pass: x = next + sign(next) * l2norm(noise_row) * EPS
//            acc += x; emb = x (for next layer); next = 0; optional cl capture
// 16 lanes per node; half-warp shfl reduction for ||noise_row||^2
// ---------------------------------------------------------------------------
__global__ void node_k(const float* __restrict__ noise_k,
                       float* __restrict__ cl_out,   // raw cl write (or null)
                       int write_cl, int last_layer) {
    unsigned t = blockIdx.x * blockDim.x + threadIdx.x;
    if (t >= (unsigned)N_NODES * 16u) return;

    float4 n4 = reinterpret_cast<const float4*>(noise_k)[t];
    float ss = n4.x * n4.x + n4.y * n4.y + n4.z * n4.z + n4.w * n4.w;
    ss += __shfl_xor_sync(0xffffffffu, ss, 1);
    ss += __shfl_xor_sync(0xffffffffu, ss, 2);
    ss += __shfl_xor_sync(0xffffffffu, ss, 4);
    ss += __shfl_xor_sync(0xffffffffu, ss, 8);
    float scale = rsqrtf(fmaxf(ss, 1e-24f)) * EPS_F;

    float4 x = reinterpret_cast<float4*>(g_next)[t];
    x.x += ((x.x > 0.f) - (x.x < 0.f)) * n4.x * scale;
    x.y += ((x.y > 0.f) - (x.y < 0.f)) * n4.y * scale;
    x.z += ((x.z > 0.f) - (x.z < 0.f)) * n4.z * scale;
    x.w += ((x.w > 0.f) - (x.w < 0.f)) * n4.w * scale;

    float4 a = reinterpret_cast<float4*>(g_acc)[t];
    a.x += x.x; a.y += x.y; a.z += x.z; a.w += x.w;
    reinterpret_cast<float4*>(g_acc)[t] = a;

    if (!last_layer) {
        reinterpret_cast<float4*>(g_emb)[t] = x;
        reinterpret_cast<float4*>(g_next)[t] = make_float4(0.f, 0.f, 0.f, 0.f);
    }
    if (write_cl)
        reinterpret_cast<float4*>(cl_out)[t] = x;
}

// ---------------------------------------------------------------------------
// final: out[0:16M)   = l2norm(acc * 0.25)   (users then items, contiguous)
//        out[16M:32M) = l2norm(cl)           (normalize in place)
// ---------------------------------------------------------------------------
__global__ void final_k(float* __restrict__ out) {
    unsigned t = blockIdx.x * blockDim.x + threadIdx.x;
    if (t >= (unsigned)N_NODES * 16u) return;

    // light_out
    float4 a = reinterpret_cast<float4*>(g_acc)[t];
    a.x *= 0.25f; a.y *= 0.25f; a.z *= 0.25f; a.w *= 0.25f;
    float ss = a.x * a.x + a.y * a.y + a.z * a.z + a.w * a.w;
    ss += __shfl_xor_sync(0xffffffffu, ss, 1);
    ss += __shfl_xor_sync(0xffffffffu, ss, 2);
    ss += __shfl_xor_sync(0xffffffffu, ss, 4);
    ss += __shfl_xor_sync(0xffffffffu, ss, 8);
    float inv = rsqrtf(fmaxf(ss, 1e-24f));
    a.x *= inv; a.y *= inv; a.z *= inv; a.w *= inv;
    reinterpret_cast<float4*>(out)[t] = a;

    // cl (raw values were stashed in the second half of out)
    float4* clp = reinterpret_cast<float4*>(out + (size_t)N_NODES * DIM);
    float4 c = clp[t];
    float cs = c.x * c.x + c.y * c.y + c.z * c.z + c.w * c.w;
    cs += __shfl_xor_sync(0xffffffffu, cs, 1);
    cs += __shfl_xor_sync(0xffffffffu, cs, 2);
    cs += __shfl_xor_sync(0xffffffffu, cs, 4);
    cs += __shfl_xor_sync(0xffffffffu, cs, 8);
    float cinv = rsqrtf(fmaxf(cs, 1e-24f));
    c.x *= cinv; c.y *= cinv; c.z *= cinv; c.w *= cinv;
    clp[t] = c;
}

extern "C" void kernel_launch(void* const* d_in, const int* in_sizes, int n_in,
                              void* d_out, int out_size) {
    const float* user_emb = (const float*)d_in[0];
    const float* item_emb = (const float*)d_in[1];
    const float* vals     = (const float*)d_in[2];
    const float* noise    = (const float*)d_in[3];
    const int*   src      = (const int*)d_in[4];
    const int*   dst      = (const int*)d_in[5];
    float* out = (float*)d_out;
    float* cl_out = out + (size_t)N_NODES * DIM;

    const int TB = 256;
    const unsigned node_threads = (unsigned)N_NODES * 16u;       // 4M
    const unsigned edge_threads = (unsigned)N_EDGES * 16u;       // 32M
    const int node_blocks = (node_threads + TB - 1) / TB;        // 15625
    const int edge_blocks = (edge_threads + TB - 1) / TB;        // 125000

    init_k<<<node_blocks, TB>>>(user_emb, item_emb);

    for (int k = 0; k < 3; k++) {
        scatter_k<<<edge_blocks, TB>>>(src, dst, vals);
        const float* noise_k = noise + (size_t)k * N_NODES * DIM;
        node_k<<<node_blocks, TB>>>(noise_k, cl_out,
                                    /*write_cl=*/(k == 0) ? 1 : 0,
                                    /*last_layer=*/(k == 2) ? 1 : 0);
    }

    final_k<<<node_blocks, TB>>>(out);
}

// round 3
// speedup vs baseline: 1.1135x; 1.1135x over previous
#include <cuda_runtime.h>
#include <cstdint>

#define NUM_USERS 100000
#define NUM_ITEMS 150000
#define N_NODES   250000
#define DIM       64
#define N_EDGES   2000000
#define EPS_F     0.2f

// Scratch (device globals: allocation-free, graph-capturable)
__device__ float g_emb [(size_t)N_NODES * DIM];  // current layer input
__device__ float g_next[(size_t)N_NODES * DIM];  // scatter target (pre-zeroed)
__device__ float g_acc [(size_t)N_NODES * DIM];  // running sum of layers

// ---------------------------------------------------------------------------
// init: emb = acc = concat(user_emb, item_emb); next = 0
// 16 lanes (float4 chunks) per node
// ---------------------------------------------------------------------------
__global__ void init_k(const float* __restrict__ ue, const float* __restrict__ ie) {
    unsigned t = blockIdx.x * blockDim.x + threadIdx.x;
    if (t >= (unsigned)N_NODES * 16u) return;
    unsigned node = t >> 4;
    unsigned c = t & 15u;
    float4 v;
    if (node < NUM_USERS)
        v = reinterpret_cast<const float4*>(ue)[(size_t)node * 16 + c];
    else
        v = reinterpret_cast<const float4*>(ie)[(size_t)(node - NUM_USERS) * 16 + c];
    reinterpret_cast<float4*>(g_emb)[t] = v;
    reinterpret_cast<float4*>(g_acc)[t] = v;
    reinterpret_cast<float4*>(g_next)[t] = make_float4(0.f, 0.f, 0.f, 0.f);
}

// ---------------------------------------------------------------------------
// scatter (half-dim pass): next[dst][cols] += vals[e] * emb[src][cols]
// 8 lanes per edge, one float4 each, covering 32 of the 64 columns.
// Working set per pass: 32MB emb-half + 32MB next-half + 24MB edges < L2.
// ---------------------------------------------------------------------------
__global__ void __launch_bounds__(256) scatter_half_k(
        const int* __restrict__ src,
        const int* __restrict__ dst,
        const float* __restrict__ vals,
        int c_off)   // 0 or 8 (float4 units)
{
    unsigned t = blockIdx.x * blockDim.x + threadIdx.x;
    unsigned e = t >> 3;
    if (e >= (unsigned)N_EDGES) return;
    unsigned c = (t & 7u) + (unsigned)c_off;
    int s = __ldg(src + e);
    int d = __ldg(dst + e);
    float v = __ldg(vals + e);
    float4 x = reinterpret_cast<const float4*>(g_emb)[(size_t)s * 16 + c];
    x.x *= v; x.y *= v; x.z *= v; x.w *= v;
    float4* p = reinterpret_cast<float4*>(g_next) + (size_t)d * 16 + c;
    asm volatile("red.global.add.v4.f32 [%0], {%1, %2, %3, %4};"
                 :: "l"(p), "f"(x.x), "f"(x.y), "f"(x.z), "f"(x.w)
                 : "memory");
}

// ---------------------------------------------------------------------------
// node pass: x = next + sign(next) * l2norm(noise_row) * EPS
//   k=0: acc += x; emb = x; next = 0; cl_out = l2norm(x)  (normalized!)
//   k=1: acc += x; emb = x; next = 0
//   k=2: out = l2norm((acc + x) * 0.25)   -- fused final, no scratch writeback
// 16 lanes per node; half-warp shfl reductions.
// ---------------------------------------------------------------------------
__device__ __forceinline__ float halfwarp_sum(float ss) {
    ss += __shfl_xor_sync(0xffffffffu, ss, 1);
    ss += __shfl_xor_sync(0xffffffffu, ss, 2);
    ss += __shfl_xor_sync(0xffffffffu, ss, 4);
    ss += __shfl_xor_sync(0xffffffffu, ss, 8);
    return ss;
}

__global__ void __launch_bounds__(256) node_k(
        const float* __restrict__ noise_k,
        float* __restrict__ out,      // used when k==2
        float* __restrict__ cl_out,   // used when k==0
        int k)
{
    unsigned t = blockIdx.x * blockDim.x + threadIdx.x;
    if (t >= (unsigned)N_NODES * 16u) return;

    float4 n4 = reinterpret_cast<const float4*>(noise_k)[t];
    float ss = halfwarp_sum(n4.x * n4.x + n4.y * n4.y + n4.z * n4.z + n4.w * n4.w);
    float scale = rsqrtf(fmaxf(ss, 1e-24f)) * EPS_F;

    float4 x = reinterpret_cast<float4*>(g_next)[t];
    x.x += (float)((x.x > 0.f) - (x.x < 0.f)) * n4.x * scale;
    x.y += (float)((x.y > 0.f) - (x.y < 0.f)) * n4.y * scale;
    x.z += (float)((x.z > 0.f) - (x.z < 0.f)) * n4.z * scale;
    x.w += (float)((x.w > 0.f) - (x.w < 0.f)) * n4.w * scale;

    float4 a = reinterpret_cast<float4*>(g_acc)[t];
    a.x += x.x; a.y += x.y; a.z += x.z; a.w += x.w;

    if (k == 2) {
        // fused final: light_out = l2norm(acc * 0.25)
        a.x *= 0.25f; a.y *= 0.25f; a.z *= 0.25f; a.w *= 0.25f;
        float s2 = halfwarp_sum(a.x * a.x + a.y * a.y + a.z * a.z + a.w * a.w);
        float inv = rsqrtf(fmaxf(s2, 1e-24f));
        a.x *= inv; a.y *= inv; a.z *= inv; a.w *= inv;
        reinterpret_cast<float4*>(out)[t] = a;
        return;  // no scratch writeback needed on last layer
    }

    reinterpret_cast<float4*>(g_acc)[t] = a;
    reinterpret_cast<float4*>(g_emb)[t] = x;
    reinterpret_cast<float4*>(g_next)[t] = make_float4(0.f, 0.f, 0.f, 0.f);

    if (k == 0) {
        // fused cl normalization: cl = l2norm(x)
        float s2 = halfwarp_sum(x.x * x.x + x.y * x.y + x.z * x.z + x.w * x.w);
        float inv = rsqrtf(fmaxf(s2, 1e-24f));
        x.x *= inv; x.y *= inv; x.z *= inv; x.w *= inv;
        reinterpret_cast<float4*>(cl_out)[t] = x;
    }
}

extern "C" void kernel_launch(void* const* d_in, const int* in_sizes, int n_in,
                              void* d_out, int out_size) {
    const float* user_emb = (const float*)d_in[0];
    const float* item_emb = (const float*)d_in[1];
    const float* vals     = (const float*)d_in[2];
    const float* noise    = (const float*)d_in[3];
    const int*   src      = (const int*)d_in[4];
    const int*   dst      = (const int*)d_in[5];
    float* out = (float*)d_out;
    float* cl_out = out + (size_t)N_NODES * DIM;

    const int TB = 256;
    const unsigned node_threads = (unsigned)N_NODES * 16u;        // 4M
    const unsigned half_threads = (unsigned)N_EDGES * 8u;         // 16M
    const int node_blocks = (node_threads + TB - 1) / TB;         // 15625
    const int half_blocks = (half_threads + TB - 1) / TB;         // 62500

    init_k<<<node_blocks, TB>>>(user_emb, item_emb);

    for (int k = 0; k < 3; k++) {
        // two half-dim passes; each has an L2-resident working set
        scatter_half_k<<<half_blocks, TB>>>(src, dst, vals, 0);
        scatter_half_k<<<half_blocks, TB>>>(src, dst, vals, 8);
        const float* noise_k = noise + (size_t)k * N_NODES * DIM;
        node_k<<<node_blocks, TB>>>(noise_k, out, cl_out, k);
    }
}

// round 4
// speedup vs baseline: 1.4202x; 1.2755x over previous
#include <cuda_runtime.h>
#include <cstdint>

#define NUM_USERS 100000
#define NUM_ITEMS 150000
#define N_NODES   250000
#define DIM       64
#define N_EDGES   2000000
#define EPS_F     0.2f

// Scratch (device globals: allocation-free, graph-capturable)
__device__ float g_emb [(size_t)N_NODES * DIM];  // current layer input (layers 1,2)
__device__ float g_next[(size_t)N_NODES * DIM];  // scatter target (pre-zeroed)
__device__ float g_acc [(size_t)N_NODES * DIM];  // running sum of layers

// ---------------------------------------------------------------------------
// zero g_next only (init/acc/emb fused away into layer-0 kernels)
// ---------------------------------------------------------------------------
__global__ void zero_next_k() {
    unsigned t = blockIdx.x * blockDim.x + threadIdx.x;
    if (t >= (unsigned)N_NODES * 16u) return;
    reinterpret_cast<float4*>(g_next)[t] = make_float4(0.f, 0.f, 0.f, 0.f);
}

// ---------------------------------------------------------------------------
// scatter (half-dim pass, 4 edges per thread):
//   next[dst][cols] += vals[e] * emb[src][cols]
// 8 lanes per edge-group of 4, one float4 column each.
// Layer 0 gathers directly from the input embeddings (no init pass).
// Working set per pass: 32MB emb-half + 32MB next-half + edges < L2.
// ---------------------------------------------------------------------------
__device__ __forceinline__ float4 gather_emb(
        int node, unsigned c, int layer0,
        const float4* __restrict__ ue, const float4* __restrict__ ie)
{
    if (layer0) {
        const float4* b = (node < NUM_USERS)
            ? (ue + (size_t)node * 16)
            : (ie + (size_t)(node - NUM_USERS) * 16);
        return __ldg(b + c);
    }
    return reinterpret_cast<const float4*>(g_emb)[(size_t)node * 16 + c];
}

__global__ void __launch_bounds__(256) scatter_half_k(
        const int* __restrict__ src,
        const int* __restrict__ dst,
        const float* __restrict__ vals,
        const float4* __restrict__ ue,
        const float4* __restrict__ ie,
        int c_off,    // 0 or 8 (float4 units)
        int layer0)
{
    unsigned t = blockIdx.x * blockDim.x + threadIdx.x;
    unsigned g = t >> 3;                       // edge group of 4
    if (g >= (unsigned)(N_EDGES / 4)) return;
    unsigned c = (t & 7u) + (unsigned)c_off;

    int4   s4 = __ldg(reinterpret_cast<const int4*>(src) + g);
    int4   d4 = __ldg(reinterpret_cast<const int4*>(dst) + g);
    float4 v4 = __ldg(reinterpret_cast<const float4*>(vals) + g);

    // 4 independent gathers in flight (MLP=4)
    float4 x0 = gather_emb(s4.x, c, layer0, ue, ie);
    float4 x1 = gather_emb(s4.y, c, layer0, ue, ie);
    float4 x2 = gather_emb(s4.z, c, layer0, ue, ie);
    float4 x3 = gather_emb(s4.w, c, layer0, ue, ie);

    x0.x *= v4.x; x0.y *= v4.x; x0.z *= v4.x; x0.w *= v4.x;
    x1.x *= v4.y; x1.y *= v4.y; x1.z *= v4.y; x1.w *= v4.y;
    x2.x *= v4.z; x2.y *= v4.z; x2.z *= v4.z; x2.w *= v4.z;
    x3.x *= v4.w; x3.y *= v4.w; x3.z *= v4.w; x3.w *= v4.w;

    float4* base = reinterpret_cast<float4*>(g_next);
    float4* p0 = base + (size_t)d4.x * 16 + c;
    float4* p1 = base + (size_t)d4.y * 16 + c;
    float4* p2 = base + (size_t)d4.z * 16 + c;
    float4* p3 = base + (size_t)d4.w * 16 + c;
    asm volatile("red.global.add.v4.f32 [%0], {%1, %2, %3, %4};"
                 :: "l"(p0), "f"(x0.x), "f"(x0.y), "f"(x0.z), "f"(x0.w) : "memory");
    asm volatile("red.global.add.v4.f32 [%0], {%1, %2, %3, %4};"
                 :: "l"(p1), "f"(x1.x), "f"(x1.y), "f"(x1.z), "f"(x1.w) : "memory");
    asm volatile("red.global.add.v4.f32 [%0], {%1, %2, %3, %4};"
                 :: "l"(p2), "f"(x2.x), "f"(x2.y), "f"(x2.z), "f"(x2.w) : "memory");
    asm volatile("red.global.add.v4.f32 [%0], {%1, %2, %3, %4};"
                 :: "l"(p3), "f"(x3.x), "f"(x3.y), "f"(x3.z), "f"(x3.w) : "memory");
}

// ---------------------------------------------------------------------------
// node pass: x = next + sign(next) * l2norm(noise_row) * EPS
//   k=0: acc = e0 + x (e0 read from inputs); emb = x; next = 0; cl = l2norm(x)
//   k=1: acc += x; emb = x; next = 0
//   k=2: out = l2norm((acc + x) * 0.25)   -- fused final, no scratch writeback
// 16 lanes per node; half-warp shfl reductions.
// ---------------------------------------------------------------------------
__device__ __forceinline__ float halfwarp_sum(float ss) {
    ss += __shfl_xor_sync(0xffffffffu, ss, 1);
    ss += __shfl_xor_sync(0xffffffffu, ss, 2);
    ss += __shfl_xor_sync(0xffffffffu, ss, 4);
    ss += __shfl_xor_sync(0xffffffffu, ss, 8);
    return ss;
}

__global__ void __launch_bounds__(256) node_k(
        const float* __restrict__ noise_k,
        const float4* __restrict__ ue,
        const float4* __restrict__ ie,
        float* __restrict__ out,      // used when k==2
        float* __restrict__ cl_out,   // used when k==0
        int k)
{
    unsigned t = blockIdx.x * blockDim.x + threadIdx.x;
    if (t >= (unsigned)N_NODES * 16u) return;

    float4 n4 = reinterpret_cast<const float4*>(noise_k)[t];
    float ss = halfwarp_sum(n4.x * n4.x + n4.y * n4.y + n4.z * n4.z + n4.w * n4.w);
    float scale = rsqrtf(fmaxf(ss, 1e-24f)) * EPS_F;

    float4 x = reinterpret_cast<float4*>(g_next)[t];
    x.x += (float)((x.x > 0.f) - (x.x < 0.f)) * n4.x * scale;
    x.y += (float)((x.y > 0.f) - (x.y < 0.f)) * n4.y * scale;
    x.z += (float)((x.z > 0.f) - (x.z < 0.f)) * n4.z * scale;
    x.w += (float)((x.w > 0.f) - (x.w < 0.f)) * n4.w * scale;

    float4 a;
    if (k == 0) {
        unsigned node = t >> 4;
        unsigned c = t & 15u;
        a = (node < NUM_USERS)
            ? __ldg(ue + (size_t)node * 16 + c)
            : __ldg(ie + (size_t)(node - NUM_USERS) * 16 + c);
    } else {
        a = reinterpret_cast<float4*>(g_acc)[t];
    }
    a.x += x.x; a.y += x.y; a.z += x.z; a.w += x.w;

    if (k == 2) {
        // fused final: light_out = l2norm(acc * 0.25)
        a.x *= 0.25f; a.y *= 0.25f; a.z *= 0.25f; a.w *= 0.25f;
        float s2 = halfwarp_sum(a.x * a.x + a.y * a.y + a.z * a.z + a.w * a.w);
        float inv = rsqrtf(fmaxf(s2, 1e-24f));
        a.x *= inv; a.y *= inv; a.z *= inv; a.w *= inv;
        reinterpret_cast<float4*>(out)[t] = a;
        return;  // no scratch writeback on last layer
    }

    reinterpret_cast<float4*>(g_acc)[t] = a;
    reinterpret_cast<float4*>(g_emb)[t] = x;
    reinterpret_cast<float4*>(g_next)[t] = make_float4(0.f, 0.f, 0.f, 0.f);

    if (k == 0) {
        // fused cl normalization: cl = l2norm(x)
        float s2 = halfwarp_sum(x.x * x.x + x.y * x.y + x.z * x.z + x.w * x.w);
        float inv = rsqrtf(fmaxf(s2, 1e-24f));
        x.x *= inv; x.y *= inv; x.z *= inv; x.w *= inv;
        reinterpret_cast<float4*>(cl_out)[t] = x;
    }
}

extern "C" void kernel_launch(void* const* d_in, const int* in_sizes, int n_in,
                              void* d_out, int out_size) {
    const float* user_emb = (const float*)d_in[0];
    const float* item_emb = (const float*)d_in[1];
    const float* vals     = (const float*)d_in[2];
    const float* noise    = (const float*)d_in[3];
    const int*   src      = (const int*)d_in[4];
    const int*   dst      = (const int*)d_in[5];
    float* out = (float*)d_out;
    float* cl_out = out + (size_t)N_NODES * DIM;
    const float4* ue4 = (const float4*)user_emb;
    const float4* ie4 = (const float4*)item_emb;

    const int TB = 256;
    const unsigned node_threads = (unsigned)N_NODES * 16u;        // 4M
    const unsigned half_threads = (unsigned)(N_EDGES / 4) * 8u;   // 4M
    const int node_blocks = (node_threads + TB - 1) / TB;         // 15625
    const int half_blocks = (half_threads + TB - 1) / TB;         // 15625

    zero_next_k<<<node_blocks, TB>>>();

    for (int k = 0; k < 3; k++) {
        int layer0 = (k == 0) ? 1 : 0;
        // two half-dim passes; each has an L2-resident working set
        scatter_half_k<<<half_blocks, TB>>>(src, dst, vals, ue4, ie4, 0, layer0);
        scatter_half_k<<<half_blocks, TB>>>(src, dst, vals, ue4, ie4, 8, layer0);
        const float* noise_k = noise + (size_t)k * N_NODES * DIM;
        node_k<<<node_blocks, TB>>>(noise_k, ue4, ie4, out, cl_out, k);
    }
}

// round 5
// speedup vs baseline: 1.4628x; 1.0300x over previous
#include <cuda_runtime.h>
#include <cstdint>

#define NUM_USERS 100000
#define NUM_ITEMS 150000
#define N_NODES   250000
#define DIM       64
#define N_EDGES   2000000
#define EPS_F     0.2f

// Ping-pong scratch buffers (device globals: allocation-free, graph-capturable)
// Layer flow: scatter(inputs)->A, x0=f(A) in place; scatter(A)->B, x1=f(B) in
// place; scatter(B)->C, x2=f(C) consumed by the fused final.
__device__ float g_A[(size_t)N_NODES * DIM];
__device__ float g_B[(size_t)N_NODES * DIM];
__device__ float g_C[(size_t)N_NODES * DIM];

__device__ __forceinline__ float4* buf_ptr(int id) {
    return id == 0 ? reinterpret_cast<float4*>(g_A)
         : id == 1 ? reinterpret_cast<float4*>(g_B)
                   : reinterpret_cast<float4*>(g_C);
}

// ---------------------------------------------------------------------------
// zero buffer A before the first scatter (B, C zeroing is fused into node_k)
// ---------------------------------------------------------------------------
__global__ void zero_A_k() {
    unsigned t = blockIdx.x * blockDim.x + threadIdx.x;
    if (t >= (unsigned)N_NODES * 16u) return;
    reinterpret_cast<float4*>(g_A)[t] = make_float4(0.f, 0.f, 0.f, 0.f);
}

// ---------------------------------------------------------------------------
// scatter (half-dim pass, 8 edges per thread):
//   tgt[dst][cols] += vals[e] * x[src][cols]
// 8 lanes per edge-group-of-8, one float4 column each (32 of 64 columns).
// Layer 0 gathers directly from the input embeddings.
// Working set per pass: 32MB src-half + 32MB tgt-half + 36MB edges < L2.
// ---------------------------------------------------------------------------
__device__ __forceinline__ float4 gather_src(
        int node, unsigned c, const float4* __restrict__ from,
        const float4* __restrict__ ue, const float4* __restrict__ ie)
{
    if (from == nullptr) {  // layer 0: read inputs
        const float4* b = (node < NUM_USERS)
            ? (ue + (size_t)node * 16)
            : (ie + (size_t)(node - NUM_USERS) * 16);
        return __ldg(b + c);
    }
    return __ldg(from + (size_t)node * 16 + c);
}

__device__ __forceinline__ void red_v4(float4* p, float4 x) {
    asm volatile("red.global.add.v4.f32 [%0], {%1, %2, %3, %4};"
                 :: "l"(p), "f"(x.x), "f"(x.y), "f"(x.z), "f"(x.w) : "memory");
}

__global__ void __launch_bounds__(256) scatter_half_k(
        const int* __restrict__ src,
        const int* __restrict__ dst,
        const float* __restrict__ vals,
        const float4* __restrict__ ue,
        const float4* __restrict__ ie,
        int c_off,     // 0 or 8 (float4 units)
        int from_id,   // -1 = inputs, else buffer id
        int tgt_id)
{
    unsigned t = blockIdx.x * blockDim.x + threadIdx.x;
    unsigned g = t >> 3;                        // edge group of 8
    if (g >= (unsigned)(N_EDGES / 8)) return;
    unsigned c = (t & 7u) + (unsigned)c_off;

    const float4* from = (from_id < 0) ? nullptr : buf_ptr(from_id);
    float4* tgt = buf_ptr(tgt_id);

    int4   sa = __ldg(reinterpret_cast<const int4*>(src) + 2 * g);
    int4   sb = __ldg(reinterpret_cast<const int4*>(src) + 2 * g + 1);
    int4   da = __ldg(reinterpret_cast<const int4*>(dst) + 2 * g);
    int4   db = __ldg(reinterpret_cast<const int4*>(dst) + 2 * g + 1);
    float4 va = __ldg(reinterpret_cast<const float4*>(vals) + 2 * g);
    float4 vb = __ldg(reinterpret_cast<const float4*>(vals) + 2 * g + 1);

    // 8 independent gathers in flight (MLP=8)
    float4 x0 = gather_src(sa.x, c, from, ue, ie);
    float4 x1 = gather_src(sa.y, c, from, ue, ie);
    float4 x2 = gather_src(sa.z, c, from, ue, ie);
    float4 x3 = gather_src(sa.w, c, from, ue, ie);
    float4 x4 = gather_src(sb.x, c, from, ue, ie);
    float4 x5 = gather_src(sb.y, c, from, ue, ie);
    float4 x6 = gather_src(sb.z, c, from, ue, ie);
    float4 x7 = gather_src(sb.w, c, from, ue, ie);

    x0.x *= va.x; x0.y *= va.x; x0.z *= va.x; x0.w *= va.x;
    x1.x *= va.y; x1.y *= va.y; x1.z *= va.y; x1.w *= va.y;
    x2.x *= va.z; x2.y *= va.z; x2.z *= va.z; x2.w *= va.z;
    x3.x *= va.w; x3.y *= va.w; x3.z *= va.w; x3.w *= va.w;
    x4.x *= vb.x; x4.y *= vb.x; x4.z *= vb.x; x4.w *= vb.x;
    x5.x *= vb.y; x5.y *= vb.y; x5.z *= vb.y; x5.w *= vb.y;
    x6.x *= vb.z; x6.y *= vb.z; x6.z *= vb.z; x6.w *= vb.z;
    x7.x *= vb.w; x7.y *= vb.w; x7.z *= vb.w; x7.w *= vb.w;

    red_v4(tgt + (size_t)da.x * 16 + c, x0);
    red_v4(tgt + (size_t)da.y * 16 + c, x1);
    red_v4(tgt + (size_t)da.z * 16 + c, x2);
    red_v4(tgt + (size_t)da.w * 16 + c, x3);
    red_v4(tgt + (size_t)db.x * 16 + c, x4);
    red_v4(tgt + (size_t)db.y * 16 + c, x5);
    red_v4(tgt + (size_t)db.z * 16 + c, x6);
    red_v4(tgt + (size_t)db.w * 16 + c, x7);
}

// ---------------------------------------------------------------------------
// node passes. 16 lanes per node; half-warp shfl reductions.
//   K=0: x0 = f(A, noise0); A := x0; zero B; cl_out = l2norm(x0)
//   K=1: x1 = f(B, noise1); B := x1; zero C
//   K=2: x2 = f(C, noise2); out = l2norm((e0 + A + B + x2) * 0.25)
// ---------------------------------------------------------------------------
__device__ __forceinline__ float halfwarp_sum(float ss) {
    ss += __shfl_xor_sync(0xffffffffu, ss, 1);
    ss += __shfl_xor_sync(0xffffffffu, ss, 2);
    ss += __shfl_xor_sync(0xffffffffu, ss, 4);
    ss += __shfl_xor_sync(0xffffffffu, ss, 8);
    return ss;
}

template <int K>
__global__ void __launch_bounds__(256) node_k(
        const float* __restrict__ noise_k,
        const float4* __restrict__ ue,
        const float4* __restrict__ ie,
        float4* __restrict__ out,      // K==2
        float4* __restrict__ cl_out)   // K==0
{
    unsigned t = blockIdx.x * blockDim.x + threadIdx.x;
    if (t >= (unsigned)N_NODES * 16u) return;

    float4 n4 = __ldcs(reinterpret_cast<const float4*>(noise_k) + t);
    float ss = halfwarp_sum(n4.x * n4.x + n4.y * n4.y + n4.z * n4.z + n4.w * n4.w);
    float scale = rsqrtf(fmaxf(ss, 1e-24f)) * EPS_F;

    float4* cur = (K == 0) ? reinterpret_cast<float4*>(g_A)
                : (K == 1) ? reinterpret_cast<float4*>(g_B)
                           : reinterpret_cast<float4*>(g_C);

    float4 x = cur[t];
    x.x += (float)((x.x > 0.f) - (x.x < 0.f)) * n4.x * scale;
    x.y += (float)((x.y > 0.f) - (x.y < 0.f)) * n4.y * scale;
    x.z += (float)((x.z > 0.f) - (x.z < 0.f)) * n4.z * scale;
    x.w += (float)((x.w > 0.f) - (x.w < 0.f)) * n4.w * scale;

    if (K == 2) {
        // fused final: out = l2norm((e0 + x0 + x1 + x2) * 0.25)
        unsigned node = t >> 4;
        unsigned c = t & 15u;
        float4 e0 = (node < NUM_USERS)
            ? __ldg(ue + (size_t)node * 16 + c)
            : __ldg(ie + (size_t)(node - NUM_USERS) * 16 + c);
        float4 a0 = reinterpret_cast<const float4*>(g_A)[t];
        float4 a1 = reinterpret_cast<const float4*>(g_B)[t];
        float4 a;
        a.x = (e0.x + a0.x + a1.x + x.x) * 0.25f;
        a.y = (e0.y + a0.y + a1.y + x.y) * 0.25f;
        a.z = (e0.z + a0.z + a1.z + x.z) * 0.25f;
        a.w = (e0.w + a0.w + a1.w + x.w) * 0.25f;
        float s2 = halfwarp_sum(a.x * a.x + a.y * a.y + a.z * a.z + a.w * a.w);
        float inv = rsqrtf(fmaxf(s2, 1e-24f));
        a.x *= inv; a.y *= inv; a.z *= inv; a.w *= inv;
        __stcs(out + t, a);
        return;
    }

    cur[t] = x;  // in-place: buffer now holds x_k for later layers/final

    // zero the next layer's scatter target
    float4* nxt = (K == 0) ? reinterpret_cast<float4*>(g_B)
                           : reinterpret_cast<float4*>(g_C);
    nxt[t] = make_float4(0.f, 0.f, 0.f, 0.f);

    if (K == 0) {
        // fused cl normalization: cl = l2norm(x0)
        float s2 = halfwarp_sum(x.x * x.x + x.y * x.y + x.z * x.z + x.w * x.w);
        float inv = rsqrtf(fmaxf(s2, 1e-24f));
        x.x *= inv; x.y *= inv; x.z *= inv; x.w *= inv;
        __stcs(cl_out + t, x);
    }
}

extern "C" void kernel_launch(void* const* d_in, const int* in_sizes, int n_in,
                              void* d_out, int out_size) {
    const float* user_emb = (const float*)d_in[0];
    const float* item_emb = (const float*)d_in[1];
    const float* vals     = (const float*)d_in[2];
    const float* noise    = (const float*)d_in[3];
    const int*   src      = (const int*)d_in[4];
    const int*   dst      = (const int*)d_in[5];
    float4* out    = (float4*)d_out;
    float4* cl_out = (float4*)((float*)d_out + (size_t)N_NODES * DIM);
    const float4* ue4 = (const float4*)user_emb;
    const float4* ie4 = (const float4*)item_emb;

    const int TB = 256;
    const unsigned node_threads = (unsigned)N_NODES * 16u;        // 4M
    const unsigned half_threads = (unsigned)(N_EDGES / 8) * 8u;   // 2M
    const int node_blocks = (node_threads + TB - 1) / TB;         // 15625
    const int half_blocks = (half_threads + TB - 1) / TB;         // 7813

    zero_A_k<<<node_blocks, TB>>>();

    // layer 0: inputs -> A
    scatter_half_k<<<half_blocks, TB>>>(src, dst, vals, ue4, ie4, 0, -1, 0);
    scatter_half_k<<<half_blocks, TB>>>(src, dst, vals, ue4, ie4, 8, -1, 0);
    node_k<0><<<node_blocks, TB>>>(noise, ue4, ie4, out, cl_out);

    // layer 1: A -> B
    scatter_half_k<<<half_blocks, TB>>>(src, dst, vals, ue4, ie4, 0, 0, 1);
    scatter_half_k<<<half_blocks, TB>>>(src, dst, vals, ue4, ie4, 8, 0, 1);
    node_k<1><<<node_blocks, TB>>>(noise + (size_t)N_NODES * DIM, ue4, ie4, out, cl_out);

    // layer 2: B -> C
    scatter_half_k<<<half_blocks, TB>>>(src, dst, vals, ue4, ie4, 0, 1, 2);
    scatter_half_k<<<half_blocks, TB>>>(src, dst, vals, ue4, ie4, 8, 1, 2);
    node_k<2><<<node_blocks, TB>>>(noise + 2 * (size_t)N_NODES * DIM, ue4, ie4, out, cl_out);
}

// round 7
// speedup vs baseline: 2.2296x; 1.5242x over previous
#include <cuda_runtime.h>
#include <cstdint>

#define NUM_USERS 100000
#define NUM_ITEMS 150000
#define N_NODES   250000
#define DIM       64
#define N_EDGES   2000000
#define EPS_F     0.2f

#define SCAN_B    512
#define N_SCAN_BLK ((N_NODES + SCAN_B - 1) / SCAN_B)   // 489

// ---------------------------------------------------------------------------
// Device scratch (allocation-free, graph-capturable)
// ---------------------------------------------------------------------------
__device__ unsigned g_cnt[N_NODES];        // in-degree per node
__device__ unsigned g_off[N_NODES];        // CSR row starts (exclusive scan)
__device__ unsigned g_cur[N_NODES];        // fill cursors
__device__ unsigned g_bsum[SCAN_B];        // block sums for the scan
__device__ uint2    g_edges[N_EDGES];      // dst-sorted: {src, val_bits}
__device__ float    g_A[(size_t)N_NODES * DIM];  // x0
__device__ float    g_B[(size_t)N_NODES * DIM];  // x1

// ---------------------------------------------------------------------------
// CSR build
// ---------------------------------------------------------------------------
__global__ void zero_cnt_k() {
    unsigned i = blockIdx.x * blockDim.x + threadIdx.x;
    if (i < N_NODES) { g_cnt[i] = 0u; }
}

__global__ void hist_k(const int* __restrict__ dst) {
    unsigned g = blockIdx.x * blockDim.x + threadIdx.x;
    if (g >= (unsigned)(N_EDGES / 4)) return;
    int4 d4 = __ldg(reinterpret_cast<const int4*>(dst) + g);
    atomicAdd(&g_cnt[d4.x], 1u);
    atomicAdd(&g_cnt[d4.y], 1u);
    atomicAdd(&g_cnt[d4.z], 1u);
    atomicAdd(&g_cnt[d4.w], 1u);
}

__global__ void scan1_k() {
    __shared__ unsigned sm[SCAN_B];
    unsigned i = blockIdx.x * SCAN_B + threadIdx.x;
    unsigned v = (i < N_NODES) ? g_cnt[i] : 0u;
    sm[threadIdx.x] = v;
    __syncthreads();
    for (int ofs = 1; ofs < SCAN_B; ofs <<= 1) {
        unsigned add = (threadIdx.x >= (unsigned)ofs) ? sm[threadIdx.x - ofs] : 0u;
        __syncthreads();
        sm[threadIdx.x] += add;
        __syncthreads();
    }
    unsigned incl = sm[threadIdx.x];
    if (i < N_NODES) g_off[i] = incl - v;            // exclusive within block
    if (threadIdx.x == SCAN_B - 1) g_bsum[blockIdx.x] = incl;
}

__global__ void scan2_k() {
    __shared__ unsigned sm[SCAN_B];
    unsigned v = (threadIdx.x < N_SCAN_BLK) ? g_bsum[threadIdx.x] : 0u;
    sm[threadIdx.x] = v;
    __syncthreads();
    for (int ofs = 1; ofs < SCAN_B; ofs <<= 1) {
        unsigned add = (threadIdx.x >= (unsigned)ofs) ? sm[threadIdx.x - ofs] : 0u;
        __syncthreads();
        sm[threadIdx.x] += add;
        __syncthreads();
    }
    if (threadIdx.x < N_SCAN_BLK) g_bsum[threadIdx.x] = sm[threadIdx.x] - v;  // exclusive
}

__global__ void scan3_k() {
    unsigned i = blockIdx.x * blockDim.x + threadIdx.x;
    if (i >= N_NODES) return;
    unsigned val = g_off[i] + g_bsum[i / SCAN_B];
    g_off[i] = val;
    g_cur[i] = val;
}

__global__ void fill_k(const int* __restrict__ src,
                       const int* __restrict__ dst,
                       const float* __restrict__ vals) {
    unsigned g = blockIdx.x * blockDim.x + threadIdx.x;
    if (g >= (unsigned)(N_EDGES / 4)) return;
    int4   s4 = __ldg(reinterpret_cast<const int4*>(src) + g);
    int4   d4 = __ldg(reinterpret_cast<const int4*>(dst) + g);
    float4 v4 = __ldg(reinterpret_cast<const float4*>(vals) + g);
    unsigned p0 = atomicAdd(&g_cur[d4.x], 1u);
    unsigned p1 = atomicAdd(&g_cur[d4.y], 1u);
    unsigned p2 = atomicAdd(&g_cur[d4.z], 1u);
    unsigned p3 = atomicAdd(&g_cur[d4.w], 1u);
    g_edges[p0] = make_uint2((unsigned)s4.x, __float_as_uint(v4.x));
    g_edges[p1] = make_uint2((unsigned)s4.y, __float_as_uint(v4.y));
    g_edges[p2] = make_uint2((unsigned)s4.z, __float_as_uint(v4.z));
    g_edges[p3] = make_uint2((unsigned)s4.w, __float_as_uint(v4.w));
}

// ---------------------------------------------------------------------------
// Fused layer kernels: gather-reduce + noise perturbation (+ cl / final)
// 16 lanes per node, one float4 column each; unroll-4 over in-edges for MLP.
//   K=0: x0 = f(segsum(E), noise0); A := x0; cl_out = l2norm(x0)
//   K=1: x1 = f(segsum(A), noise1); B := x1
//   K=2: x2 = f(segsum(B), noise2); out = l2norm((e0 + A + B + x2) * 0.25)
// ---------------------------------------------------------------------------
__device__ __forceinline__ float halfwarp_sum(float ss) {
    ss += __shfl_xor_sync(0xffffffffu, ss, 1);
    ss += __shfl_xor_sync(0xffffffffu, ss, 2);
    ss += __shfl_xor_sync(0xffffffffu, ss, 4);
    ss += __shfl_xor_sync(0xffffffffu, ss, 8);
    return ss;
}

template <int K>
__device__ __forceinline__ const float4* src_row(
        unsigned node, const float4* __restrict__ ue, const float4* __restrict__ ie)
{
    if (K == 0) {
        return (node < NUM_USERS) ? (ue + (size_t)node * 16)
                                  : (ie + (size_t)(node - NUM_USERS) * 16);
    }
    const float* b = (K == 1) ? g_A : g_B;
    return reinterpret_cast<const float4*>(b) + (size_t)node * 16;
}

template <int K>
__global__ void __launch_bounds__(256) layer_k(
        const float* __restrict__ noise_k,
        const float4* __restrict__ ue,
        const float4* __restrict__ ie,
        float4* __restrict__ out,      // K==2
        float4* __restrict__ cl_out)   // K==0
{
    unsigned t = blockIdx.x * blockDim.x + threadIdx.x;
    if (t >= (unsigned)N_NODES * 16u) return;
    unsigned node = t >> 4;
    unsigned c = t & 15u;

    unsigned base = g_off[node];
    unsigned deg  = g_cnt[node];

    float4 s = make_float4(0.f, 0.f, 0.f, 0.f);

    // unroll-4 main loop: 4 independent gathers in flight
    unsigned i = 0;
    for (; i + 4 <= deg; i += 4) {
        uint2 e0 = __ldg(&g_edges[base + i]);
        uint2 e1 = __ldg(&g_edges[base + i + 1]);
        uint2 e2 = __ldg(&g_edges[base + i + 2]);
        uint2 e3 = __ldg(&g_edges[base + i + 3]);
        float4 x0 = __ldg(src_row<K>(e0.x, ue, ie) + c);
        float4 x1 = __ldg(src_row<K>(e1.x, ue, ie) + c);
        float4 x2 = __ldg(src_row<K>(e2.x, ue, ie) + c);
        float4 x3 = __ldg(src_row<K>(e3.x, ue, ie) + c);
        float v0 = __uint_as_float(e0.y), v1 = __uint_as_float(e1.y);
        float v2 = __uint_as_float(e2.y), v3 = __uint_as_float(e3.y);
        s.x += v0 * x0.x + v1 * x1.x + v2 * x2.x + v3 * x3.x;
        s.y += v0 * x0.y + v1 * x1.y + v2 * x2.y + v3 * x3.y;
        s.z += v0 * x0.z + v1 * x1.z + v2 * x2.z + v3 * x3.z;
        s.w += v0 * x0.w + v1 * x1.w + v2 * x2.w + v3 * x3.w;
    }
    for (; i < deg; i++) {
        uint2 e = __ldg(&g_edges[base + i]);
        float4 x = __ldg(src_row<K>(e.x, ue, ie) + c);
        float v = __uint_as_float(e.y);
        s.x += v * x.x; s.y += v * x.y; s.z += v * x.z; s.w += v * x.w;
    }

    // noise perturbation
    float4 n4 = __ldcs(reinterpret_cast<const float4*>(noise_k) + t);
    float ss = halfwarp_sum(n4.x * n4.x + n4.y * n4.y + n4.z * n4.z + n4.w * n4.w);
    float scale = rsqrtf(fmaxf(ss, 1e-24f)) * EPS_F;

    float4 x = s;
    x.x += (float)((s.x > 0.f) - (s.x < 0.f)) * n4.x * scale;
    x.y += (float)((s.y > 0.f) - (s.y < 0.f)) * n4.y * scale;
    x.z += (float)((s.z > 0.f) - (s.z < 0.f)) * n4.z * scale;
    x.w += (float)((s.w > 0.f) - (s.w < 0.f)) * n4.w * scale;

    if (K == 2) {
        // fused final: out = l2norm((e0 + x0 + x1 + x2) * 0.25)
        float4 e0 = (node < NUM_USERS)
            ? __ldg(ue + (size_t)node * 16 + c)
            : __ldg(ie + (size_t)(node - NUM_USERS) * 16 + c);
        float4 a0 = reinterpret_cast<const float4*>(g_A)[t];
        float4 a1 = reinterpret_cast<const float4*>(g_B)[t];
        float4 a;
        a.x = (e0.x + a0.x + a1.x + x.x) * 0.25f;
        a.y = (e0.y + a0.y + a1.y + x.y) * 0.25f;
        a.z = (e0.z + a0.z + a1.z + x.z) * 0.25f;
        a.w = (e0.w + a0.w + a1.w + x.w) * 0.25f;
        float s2 = halfwarp_sum(a.x * a.x + a.y * a.y + a.z * a.z + a.w * a.w);
        float inv = rsqrtf(fmaxf(s2, 1e-24f));
        a.x *= inv; a.y *= inv; a.z *= inv; a.w *= inv;
        __stcs(out + t, a);
        return;
    }

    float4* tgt = (K == 0) ? reinterpret_cast<float4*>(g_A)
                           : reinterpret_cast<float4*>(g_B);
    tgt[t] = x;

    if (K == 0) {
        float s2 = halfwarp_sum(x.x * x.x + x.y * x.y + x.z * x.z + x.w * x.w);
        float inv = rsqrtf(fmaxf(s2, 1e-24f));
        x.x *= inv; x.y *= inv; x.z *= inv; x.w *= inv;
        __stcs(cl_out + t, x);
    }
}

extern "C" void kernel_launch(void* const* d_in, const int* in_sizes, int n_in,
                              void* d_out, int out_size) {
    const float* user_emb = (const float*)d_in[0];
    const float* item_emb = (const float*)d_in[1];
    const float* vals     = (const float*)d_in[2];
    const float* noise    = (const float*)d_in[3];
    const int*   src      = (const int*)d_in[4];
    const int*   dst      = (const int*)d_in[5];
    float4* out    = (float4*)d_out;
    float4* cl_out = (float4*)((float*)d_out + (size_t)N_NODES * DIM);
    const float4* ue4 = (const float4*)user_emb;
    const float4* ie4 = (const float4*)item_emb;

    const int TB = 256;
    const int node_blk  = (N_NODES + TB - 1) / TB;                 // 977
    const int edge4_blk = (N_EDGES / 4 + TB - 1) / TB;             // 1954
    const int work_blk  = ((unsigned)N_NODES * 16u + TB - 1) / TB; // 15625

    // CSR build
    zero_cnt_k<<<node_blk, TB>>>();
    hist_k<<<edge4_blk, TB>>>(dst);
    scan1_k<<<N_SCAN_BLK, SCAN_B>>>();
    scan2_k<<<1, SCAN_B>>>();
    scan3_k<<<node_blk, TB>>>();
    fill_k<<<edge4_blk, TB>>>(src, dst, vals);

    // fused layers
    layer_k<0><<<work_blk, TB>>>(noise,                              ue4, ie4, out, cl_out);
    layer_k<1><<<work_blk, TB>>>(noise + (size_t)N_NODES * DIM,      ue4, ie4, out, cl_out);
    layer_k<2><<<work_blk, TB>>>(noise + 2 * (size_t)N_NODES * DIM,  ue4, ie4, out, cl_out);
}